// round 14
// baseline (speedup 1.0000x reference)
#include <cuda_runtime.h>
#include <cuda_fp16.h>
#include <cstdint>
#include <math.h>

// ============================================================================
// Masked SDPA flash-attention, HMMA mma.sync, fp16 single-pass GEMMs.
// B=4, L=4096, D=64. Grid 256 CTAs (BQ=64), 8 warps = (q-rowblock wq, key-half h).
// R13 (= R5 pipeline + HMMA row-sums) with the per-tile compute reordered
// p-outer so softmax/GEMM2 of score-half 0 overlaps GEMM1/softmax of half 1:
//   G1(h0) -> [G1(h1) || softmax(h0)] -> [G2(k2=0) || softmax(h1)] -> G2(k2=1)
// No-max softmax (scores bounded; Q pre-scaled by 0.125*log2e).
// ============================================================================

namespace {

constexpr int kB = 4, kL = 4096, kD = 64;
constexpr int BQ = 64, BK = 64;
constexpr int NT = kL / BK;
constexpr int NTHREADS = 256;
constexpr uint32_t kOnesH2 = 0x3C003C00u;   // half2(1.0, 1.0)

__device__ __half g_Qh[kB * kL * kD];   // pre-scaled by 0.125*log2e
__device__ __half g_Kh[kB * kL * kD];
__device__ __half g_Vh[kB * kL * kD];

// SMEM: Q 8K | KV buf0 16K | KV buf1 16K | M buf0 18K | M buf1 18K
constexpr uint32_t OFF_Q = 0;
constexpr uint32_t OFF_KV = 8192, KV_STRIDE = 16384;
constexpr uint32_t OFF_M = 40960;
constexpr uint32_t M_STRIDE = 18432;     // 64 rows * 72 floats * 4B
constexpr uint32_t M_ROW = 288;          // 72 floats
constexpr int SMEM_TOTAL = 77824;
// epilogue scratch (reuses KV region after final barrier)
constexpr uint32_t OFF_RO = 8192, OFF_RS = 24576;

__device__ __forceinline__ uint32_t smem_u32(const void* p) {
    uint32_t a;
    asm("{ .reg .u64 t; cvta.to.shared.u64 t, %1; cvt.u32.u64 %0, t; }"
        : "=r"(a) : "l"(p));
    return a;
}

__device__ __forceinline__ uint32_t swz(int r, int c) {
    return (uint32_t)r * 128u + (uint32_t)((c ^ (r & 7)) << 4);
}

#define CP16(dst, src) \
    asm volatile("cp.async.cg.shared.global [%0], [%1], 16;" \
                 :: "r"(dst), "l"(__cvta_generic_to_global(src)) : "memory")
#define CPCOMMIT() asm volatile("cp.async.commit_group;" ::: "memory")

__device__ __forceinline__ void ldsm_x4(uint32_t* r, uint32_t a) {
    asm volatile("ldmatrix.sync.aligned.m8n8.x4.shared.b16 {%0,%1,%2,%3}, [%4];"
                 : "=r"(r[0]), "=r"(r[1]), "=r"(r[2]), "=r"(r[3]) : "r"(a));
}
__device__ __forceinline__ void ldsm_x4t(uint32_t* r, uint32_t a) {
    asm volatile("ldmatrix.sync.aligned.m8n8.x4.trans.shared.b16 {%0,%1,%2,%3}, [%4];"
                 : "=r"(r[0]), "=r"(r[1]), "=r"(r[2]), "=r"(r[3]) : "r"(a));
}
__device__ __forceinline__ void mma16816(float* c, const uint32_t* a,
                                         uint32_t b0, uint32_t b1) {
    asm volatile(
        "mma.sync.aligned.m16n8k16.row.col.f32.f16.f16.f32 "
        "{%0,%1,%2,%3}, {%4,%5,%6,%7}, {%8,%9}, {%0,%1,%2,%3};"
        : "+f"(c[0]), "+f"(c[1]), "+f"(c[2]), "+f"(c[3])
        : "r"(a[0]), "r"(a[1]), "r"(a[2]), "r"(a[3]), "r"(b0), "r"(b1));
}

__device__ __forceinline__ uint32_t packh2(float x, float y) {
    __half2 h = __floats2half2_rn(x, y);
    return *reinterpret_cast<uint32_t*>(&h);
}

__device__ __forceinline__ float ex2(float x) {
    float y;
    asm("ex2.approx.f32 %0, %1;" : "=f"(y) : "f"(x));
    return y;
}

// ---------------------------------------------------------------------------
__global__ void prep_kernel(const float* __restrict__ Q,
                            const float* __restrict__ K,
                            const float* __restrict__ V) {
    int base = (blockIdx.x * blockDim.x + threadIdx.x) * 4;
    constexpr float kS = 0.125f * 1.44269504f;  // 1/sqrt(64) * log2(e)
    float4 q = *(const float4*)(Q + base);
    q.x *= kS; q.y *= kS; q.z *= kS; q.w *= kS;
    auto cvt = [](float4 x) {
        __half2 a = __floats2half2_rn(x.x, x.y);
        __half2 b = __floats2half2_rn(x.z, x.w);
        return make_uint2(*(uint32_t*)&a, *(uint32_t*)&b);
    };
    *(uint2*)(g_Qh + base) = cvt(q);
    *(uint2*)(g_Kh + base) = cvt(*(const float4*)(K + base));
    *(uint2*)(g_Vh + base) = cvt(*(const float4*)(V + base));
}

// cp.async one K/V tile (keys j0..j0+63)
__device__ __forceinline__ void kv_load(uint32_t buf, const __half* kh,
                                        const __half* vh, int j0, int tid) {
    int r = tid >> 2;
    #pragma unroll
    for (int i = 0; i < 2; i++) {
        int c = ((tid & 3) << 1) + i;
        uint32_t d = buf + swz(r, c);
        size_t g = (size_t)(j0 + r) * kD + c * 8;
        CP16(d, kh + g);
        CP16(d + 8192, vh + g);
    }
}

// cp.async one mask tile: 64 q-rows x 64 floats, smem stride 72 floats
__device__ __forceinline__ void mask_load(uint32_t mbuf, const float* Mrow,
                                          int j0, int tid) {
    int r = tid >> 2;
    uint32_t d = mbuf + (uint32_t)r * M_ROW + (uint32_t)(tid & 3) * 16u;
    const float* s = Mrow + (size_t)r * kL + j0 + (tid & 3) * 4;
    #pragma unroll
    for (int i = 0; i < 4; i++) CP16(d + 64u * i, s + 16 * i);
}

// ---------------------------------------------------------------------------
__global__ __launch_bounds__(NTHREADS, 2)
void attn_kernel(const float* __restrict__ gM, float* __restrict__ gO) {
    extern __shared__ char smem[];
    const uint32_t sb = smem_u32(smem);
    const int tid = threadIdx.x;
    const int lane = tid & 31;
    const int w = tid >> 5;
    const int wq = w & 3;                // q-row block (16 rows)
    const int h = w >> 2;                // key half (32 keys)
    const int b = blockIdx.y;
    const int q0 = blockIdx.x * BQ;

    const __half* gQh = g_Qh + (size_t)(b * kL + q0) * kD;
    const __half* gKh = g_Kh + (size_t)b * kL * kD;
    const __half* gVh = g_Vh + (size_t)b * kL * kD;
    const float* Mrow = gM + ((size_t)b * kL + q0) * kL;

    // prologue: Q (g0) | KV0+M0 (g1) | KV1+M1 (g2)
    {
        int r = tid >> 2;
        #pragma unroll
        for (int i = 0; i < 2; i++) {
            int c = ((tid & 3) << 1) + i;
            CP16(sb + OFF_Q + swz(r, c), gQh + (size_t)r * kD + c * 8);
        }
    }
    CPCOMMIT();
    kv_load(sb + OFF_KV, gKh, gVh, 0, tid);
    mask_load(sb + OFF_M, Mrow, 0, tid);
    CPCOMMIT();
    kv_load(sb + OFF_KV + KV_STRIDE, gKh, gVh, BK, tid);
    mask_load(sb + OFF_M + M_STRIDE, Mrow, BK, tid);
    CPCOMMIT();

    // per-lane fragment address components
    const int qr = ((lane >> 3) & 1) * 8 + (lane & 7);
    const int qcb = (lane >> 4) & 1;
    const int kr = ((lane >> 4) << 3) + (lane & 7);
    const int kcb = (lane >> 3) & 1;
    const uint32_t qrow = (uint32_t)(16 * wq + qr) * 128u;
    const uint32_t vrow = (uint32_t)qr * 128u;
    const uint32_t krow = (uint32_t)kr * 128u;
    const int qs = qr & 7, ks = kr & 7;

    asm volatile("cp.async.wait_group 2;" ::: "memory");
    __syncthreads();

    uint32_t qf[16];
    #pragma unroll
    for (int k = 0; k < 4; k++)
        ldsm_x4(qf + 4 * k, sb + OFF_Q + qrow + (uint32_t)(((2 * k + qcb) ^ qs) << 4));

    const int r0 = lane >> 2, c0 = (lane & 3) * 2;
    const char* mbase = smem + (size_t)(16 * wq + r0) * M_ROW +
                        (size_t)(32 * h + c0) * 4;

    float oacc[8][4];
    #pragma unroll
    for (int n = 0; n < 8; n++)
        #pragma unroll
        for (int j = 0; j < 4; j++) oacc[n][j] = 0.f;
    // row-sum accumulator via HMMA against ones
    float racc[4] = {0.f, 0.f, 0.f, 0.f};

    for (int t = 0; t < NT; t++) {
        const uint32_t kb = sb + OFF_KV + (uint32_t)(t & 1) * KV_STRIDE +
                            (uint32_t)h * 4096u;
        const uint32_t vb = kb + 8192u;
        const char* mt = mbase + OFF_M + (uint32_t)(t & 1) * M_STRIDE;

        asm volatile("cp.async.wait_group 1;" ::: "memory");
        __syncthreads();

        float sacc[4][4];
        #pragma unroll
        for (int n = 0; n < 4; n++)
            #pragma unroll
            for (int j = 0; j < 4; j++) sacc[n][j] = 0.f;

        uint32_t p01[4], p23[4];

        // ---- GEMM1 half 0: score cols 0-15 (sacc[0], sacc[1]) ----
        #pragma unroll
        for (int k = 0; k < 4; k++) {
            uint32_t off = krow + (uint32_t)(((2 * k + kcb) ^ ks) << 4);
            uint32_t kf[4];
            ldsm_x4(kf, kb + off);
            mma16816(sacc[0], qf + 4 * k, kf[0], kf[1]);
            mma16816(sacc[1], qf + 4 * k, kf[2], kf[3]);
        }

        // ---- GEMM1 half 1: score cols 16-31 (sacc[2], sacc[3]) ----
        // (independent of softmax half 0 below; scheduler may overlap)
        #pragma unroll
        for (int k = 0; k < 4; k++) {
            uint32_t off = krow + (uint32_t)(((2 * k + kcb) ^ ks) << 4);
            uint32_t kf[4];
            ldsm_x4(kf, kb + 2048u + off);
            mma16816(sacc[2], qf + 4 * k, kf[0], kf[1]);
            mma16816(sacc[3], qf + 4 * k, kf[2], kf[3]);
        }

        // ---- softmax half 0 (n = 0,1) — overlaps GEMM1 half 1 ----
        #pragma unroll
        for (int n = 0; n < 2; n++) {
            float2 m0 = *(const float2*)(mt + 32 * n);
            float2 m1 = *(const float2*)(mt + 8 * M_ROW + 32 * n);
            float e0 = ex2(sacc[n][0] * m0.x);
            float e1 = ex2(sacc[n][1] * m0.y);
            float e2 = ex2(sacc[n][2] * m1.x);
            float e3 = ex2(sacc[n][3] * m1.y);
            p01[n] = packh2(e0, e1);
            p23[n] = packh2(e2, e3);
        }

        // ---- GEMM2 k2=0 (keys 0-15 of this half) + row-sums ----
        {
            uint32_t pa[4] = {p01[0], p23[0], p01[1], p23[1]};
            mma16816(racc, pa, kOnesH2, kOnesH2);
            #pragma unroll
            for (int p = 0; p < 4; p++) {
                uint32_t vf[4];
                uint32_t off = vrow + (uint32_t)(((2 * p + qcb) ^ qs) << 4);
                ldsm_x4t(vf, vb + off);
                mma16816(oacc[2 * p],     pa, vf[0], vf[1]);
                mma16816(oacc[2 * p + 1], pa, vf[2], vf[3]);
            }
        }

        // ---- softmax half 1 (n = 2,3) — overlaps GEMM2 k2=0 ----
        #pragma unroll
        for (int n = 2; n < 4; n++) {
            float2 m0 = *(const float2*)(mt + 32 * n);
            float2 m1 = *(const float2*)(mt + 8 * M_ROW + 32 * n);
            float e0 = ex2(sacc[n][0] * m0.x);
            float e1 = ex2(sacc[n][1] * m0.y);
            float e2 = ex2(sacc[n][2] * m1.x);
            float e3 = ex2(sacc[n][3] * m1.y);
            p01[n] = packh2(e0, e1);
            p23[n] = packh2(e2, e3);
        }

        // ---- GEMM2 k2=1 (keys 16-31 of this half) + row-sums ----
        {
            uint32_t pa[4] = {p01[2], p23[2], p01[3], p23[3]};
            mma16816(racc, pa, kOnesH2, kOnesH2);
            #pragma unroll
            for (int p = 0; p < 4; p++) {
                uint32_t vf[4];
                uint32_t off = vrow + (uint32_t)(((2 * p + qcb) ^ qs) << 4);
                ldsm_x4t(vf, vb + 2048u + off);
                mma16816(oacc[2 * p],     pa, vf[0], vf[1]);
                mma16816(oacc[2 * p + 1], pa, vf[2], vf[3]);
            }
        }

        __syncthreads();
        if (t + 2 < NT) {
            kv_load(sb + OFF_KV + (uint32_t)(t & 1) * KV_STRIDE,
                    gKh, gVh, (t + 2) * BK, tid);
            mask_load(sb + OFF_M + (uint32_t)(t & 1) * M_STRIDE,
                      Mrow, (t + 2) * BK, tid);
        }
        CPCOMMIT();
    }

    // ---- epilogue: reduce key halves, normalize, store ----
    const float rs0 = racc[0];   // full row sum (this warp's 32-key half)
    const float rs1 = racc[2];

    __syncthreads();
    float* sO = (float*)(smem + OFF_RO) + wq * 1024;   // [16][64]
    float* sRS = (float*)(smem + OFF_RS);

    if (h == 1) {
        if ((lane & 3) == 0) {
            sRS[wq * 16 + r0] = rs0;
            sRS[wq * 16 + 8 + r0] = rs1;
        }
        #pragma unroll
        for (int n = 0; n < 8; n++) {
            *(float2*)(sO + r0 * 64 + 8 * n + c0) =
                make_float2(oacc[n][0], oacc[n][1]);
            *(float2*)(sO + (r0 + 8) * 64 + 8 * n + c0) =
                make_float2(oacc[n][2], oacc[n][3]);
        }
    }
    __syncthreads();

    if (h == 0) {
        float i0 = 1.f / (rs0 + sRS[wq * 16 + r0]);
        float i1 = 1.f / (rs1 + sRS[wq * 16 + 8 + r0]);
        float* o0 = gO + ((size_t)b * kL + q0 + 16 * wq + r0) * kD + c0;
        float* o1 = o0 + 8 * (size_t)kD;
        #pragma unroll
        for (int n = 0; n < 8; n++) {
            float2 a = *(const float2*)(sO + r0 * 64 + 8 * n + c0);
            float2 c = *(const float2*)(sO + (r0 + 8) * 64 + 8 * n + c0);
            *(float2*)(o0 + 8 * n) = make_float2((oacc[n][0] + a.x) * i0,
                                                 (oacc[n][1] + a.y) * i0);
            *(float2*)(o1 + 8 * n) = make_float2((oacc[n][2] + c.x) * i1,
                                                 (oacc[n][3] + c.y) * i1);
        }
    }
}

}  // namespace

extern "C" void kernel_launch(void* const* d_in, const int* in_sizes, int n_in,
                              void* d_out, int out_size) {
    const float* Q = (const float*)d_in[0];
    const float* K = (const float*)d_in[1];
    const float* V = (const float*)d_in[2];
    const float* M = (const float*)d_in[3];
    float* O = (float*)d_out;

    prep_kernel<<<1024, 256>>>(Q, K, V);

    cudaFuncSetAttribute(attn_kernel,
                         cudaFuncAttributeMaxDynamicSharedMemorySize, SMEM_TOTAL);
    dim3 grid(kL / BQ, kB);
    attn_kernel<<<grid, NTHREADS, SMEM_TOTAL>>>(M, O);
}

// round 15
// speedup vs baseline: 1.0963x; 1.0963x over previous
#include <cuda_runtime.h>
#include <cuda_fp16.h>
#include <cstdint>
#include <math.h>

// ============================================================================
// Masked SDPA flash-attention, HMMA mma.sync, fp16 single-pass GEMMs.
// B=4, L=4096, D=64. Grid 256 CTAs (BQ=64), 8 warps = (q-rowblock wq, key-half h).
// R14 body (p-outer reorder + HMMA row-sums), with THREE statically-indexed
// KV/mask slots (x3-unrolled tile loop) and ONE barrier per tile:
//   top: wait_group 1 + __syncthreads; bottom: loads for t+2 into slot (t+2)%3
//   (== slot(t-1), last read before the barrier all warps just passed).
// No-max softmax (scores bounded; Q pre-scaled by 0.125*log2e).
// ============================================================================

namespace {

constexpr int kB = 4, kL = 4096, kD = 64;
constexpr int BQ = 64, BK = 64;
constexpr int NT = kL / BK;            // 64
constexpr int NTHREADS = 256;
constexpr uint32_t kOnesH2 = 0x3C003C00u;   // half2(1.0, 1.0)

__device__ __half g_Qh[kB * kL * kD];   // pre-scaled by 0.125*log2e
__device__ __half g_Kh[kB * kL * kD];
__device__ __half g_Vh[kB * kL * kD];

// SMEM: Q 8K | KV slots 0..2 (16K each) | M slots 0..2 (18K each)
constexpr uint32_t OFF_Q = 0;
constexpr uint32_t OFF_KV = 8192, KV_STRIDE = 16384;
constexpr uint32_t OFF_M = 8192 + 3 * 16384;           // 57344
constexpr uint32_t M_STRIDE = 18432;                   // 64 rows * 72 floats * 4B
constexpr uint32_t M_ROW = 288;                        // 72 floats
constexpr int SMEM_TOTAL = (int)(OFF_M + 3 * M_STRIDE);  // 112640
// epilogue scratch (reuses KV region after final barrier)
constexpr uint32_t OFF_RO = 8192, OFF_RS = 24576;

__device__ __forceinline__ uint32_t smem_u32(const void* p) {
    uint32_t a;
    asm("{ .reg .u64 t; cvta.to.shared.u64 t, %1; cvt.u32.u64 %0, t; }"
        : "=r"(a) : "l"(p));
    return a;
}

__device__ __forceinline__ uint32_t swz(int r, int c) {
    return (uint32_t)r * 128u + (uint32_t)((c ^ (r & 7)) << 4);
}

#define CP16(dst, src) \
    asm volatile("cp.async.cg.shared.global [%0], [%1], 16;" \
                 :: "r"(dst), "l"(__cvta_generic_to_global(src)) : "memory")
#define CPCOMMIT() asm volatile("cp.async.commit_group;" ::: "memory")

__device__ __forceinline__ void ldsm_x4(uint32_t* r, uint32_t a) {
    asm volatile("ldmatrix.sync.aligned.m8n8.x4.shared.b16 {%0,%1,%2,%3}, [%4];"
                 : "=r"(r[0]), "=r"(r[1]), "=r"(r[2]), "=r"(r[3]) : "r"(a));
}
__device__ __forceinline__ void ldsm_x4t(uint32_t* r, uint32_t a) {
    asm volatile("ldmatrix.sync.aligned.m8n8.x4.trans.shared.b16 {%0,%1,%2,%3}, [%4];"
                 : "=r"(r[0]), "=r"(r[1]), "=r"(r[2]), "=r"(r[3]) : "r"(a));
}
__device__ __forceinline__ void mma16816(float* c, const uint32_t* a,
                                         uint32_t b0, uint32_t b1) {
    asm volatile(
        "mma.sync.aligned.m16n8k16.row.col.f32.f16.f16.f32 "
        "{%0,%1,%2,%3}, {%4,%5,%6,%7}, {%8,%9}, {%0,%1,%2,%3};"
        : "+f"(c[0]), "+f"(c[1]), "+f"(c[2]), "+f"(c[3])
        : "r"(a[0]), "r"(a[1]), "r"(a[2]), "r"(a[3]), "r"(b0), "r"(b1));
}

__device__ __forceinline__ uint32_t packh2(float x, float y) {
    __half2 h = __floats2half2_rn(x, y);
    return *reinterpret_cast<uint32_t*>(&h);
}

__device__ __forceinline__ float ex2(float x) {
    float y;
    asm("ex2.approx.f32 %0, %1;" : "=f"(y) : "f"(x));
    return y;
}

// ---------------------------------------------------------------------------
__global__ void prep_kernel(const float* __restrict__ Q,
                            const float* __restrict__ K,
                            const float* __restrict__ V) {
    int base = (blockIdx.x * blockDim.x + threadIdx.x) * 4;
    constexpr float kS = 0.125f * 1.44269504f;  // 1/sqrt(64) * log2(e)
    float4 q = *(const float4*)(Q + base);
    q.x *= kS; q.y *= kS; q.z *= kS; q.w *= kS;
    auto cvt = [](float4 x) {
        __half2 a = __floats2half2_rn(x.x, x.y);
        __half2 b = __floats2half2_rn(x.z, x.w);
        return make_uint2(*(uint32_t*)&a, *(uint32_t*)&b);
    };
    *(uint2*)(g_Qh + base) = cvt(q);
    *(uint2*)(g_Kh + base) = cvt(*(const float4*)(K + base));
    *(uint2*)(g_Vh + base) = cvt(*(const float4*)(V + base));
}

// cp.async one K/V tile (keys j0..j0+63)
__device__ __forceinline__ void kv_load(uint32_t buf, const __half* kh,
                                        const __half* vh, int j0, int tid) {
    int r = tid >> 2;
    #pragma unroll
    for (int i = 0; i < 2; i++) {
        int c = ((tid & 3) << 1) + i;
        uint32_t d = buf + swz(r, c);
        size_t g = (size_t)(j0 + r) * kD + c * 8;
        CP16(d, kh + g);
        CP16(d + 8192, vh + g);
    }
}

// cp.async one mask tile: 64 q-rows x 64 floats, smem stride 72 floats
__device__ __forceinline__ void mask_load(uint32_t mbuf, const float* Mrow,
                                          int j0, int tid) {
    int r = tid >> 2;
    uint32_t d = mbuf + (uint32_t)r * M_ROW + (uint32_t)(tid & 3) * 16u;
    const float* s = Mrow + (size_t)r * kL + j0 + (tid & 3) * 4;
    #pragma unroll
    for (int i = 0; i < 4; i++) CP16(d + 64u * i, s + 16 * i);
}

// ---------------------------------------------------------------------------
__global__ __launch_bounds__(NTHREADS, 2)
void attn_kernel(const float* __restrict__ gM, float* __restrict__ gO) {
    extern __shared__ char smem[];
    const uint32_t sb = smem_u32(smem);
    const int tid = threadIdx.x;
    const int lane = tid & 31;
    const int w = tid >> 5;
    const int wq = w & 3;                // q-row block (16 rows)
    const int h = w >> 2;                // key half (32 keys)
    const int b = blockIdx.y;
    const int q0 = blockIdx.x * BQ;

    const __half* gQh = g_Qh + (size_t)(b * kL + q0) * kD;
    const __half* gKh = g_Kh + (size_t)b * kL * kD;
    const __half* gVh = g_Vh + (size_t)b * kL * kD;
    const float* Mrow = gM + ((size_t)b * kL + q0) * kL;

    // prologue: Q (g0) | KV0+M0 -> slot0 (g1) | KV1+M1 -> slot1 (g2)
    {
        int r = tid >> 2;
        #pragma unroll
        for (int i = 0; i < 2; i++) {
            int c = ((tid & 3) << 1) + i;
            CP16(sb + OFF_Q + swz(r, c), gQh + (size_t)r * kD + c * 8);
        }
    }
    CPCOMMIT();
    kv_load(sb + OFF_KV, gKh, gVh, 0, tid);
    mask_load(sb + OFF_M, Mrow, 0, tid);
    CPCOMMIT();
    kv_load(sb + OFF_KV + KV_STRIDE, gKh, gVh, BK, tid);
    mask_load(sb + OFF_M + M_STRIDE, Mrow, BK, tid);
    CPCOMMIT();

    // per-lane fragment address components
    const int qr = ((lane >> 3) & 1) * 8 + (lane & 7);
    const int qcb = (lane >> 4) & 1;
    const int kr = ((lane >> 4) << 3) + (lane & 7);
    const int kcb = (lane >> 3) & 1;
    const uint32_t qrow = (uint32_t)(16 * wq + qr) * 128u;
    const uint32_t vrow = (uint32_t)qr * 128u;
    const uint32_t krow = (uint32_t)kr * 128u;
    const int qs = qr & 7, ks = kr & 7;

    asm volatile("cp.async.wait_group 2;" ::: "memory");
    __syncthreads();

    uint32_t qf[16];
    #pragma unroll
    for (int k = 0; k < 4; k++)
        ldsm_x4(qf + 4 * k, sb + OFF_Q + qrow + (uint32_t)(((2 * k + qcb) ^ qs) << 4));

    const int r0 = lane >> 2, c0 = (lane & 3) * 2;
    const char* mbase = smem + (size_t)(16 * wq + r0) * M_ROW +
                        (size_t)(32 * h + c0) * 4;

    float oacc[8][4];
    #pragma unroll
    for (int n = 0; n < 8; n++)
        #pragma unroll
        for (int j = 0; j < 4; j++) oacc[n][j] = 0.f;
    float racc[4] = {0.f, 0.f, 0.f, 0.f};

    // One tile: slot constants are compile-time (SLOT, WSLOT).
    #define TILE_BODY(T, SLOT, WSLOT)                                          \
    do {                                                                       \
        const uint32_t kb = sb + OFF_KV + (uint32_t)(SLOT) * KV_STRIDE +       \
                            (uint32_t)h * 4096u;                               \
        const uint32_t vb = kb + 8192u;                                        \
        const char* mt = mbase + OFF_M + (uint32_t)(SLOT) * M_STRIDE;          \
        asm volatile("cp.async.wait_group 1;" ::: "memory");                   \
        __syncthreads();                                                       \
        float sacc[4][4];                                                      \
        _Pragma("unroll")                                                      \
        for (int n = 0; n < 4; n++)                                            \
            _Pragma("unroll")                                                  \
            for (int j = 0; j < 4; j++) sacc[n][j] = 0.f;                      \
        uint32_t p01[4], p23[4];                                               \
        _Pragma("unroll")                                                      \
        for (int k = 0; k < 4; k++) {                                          \
            uint32_t off = krow + (uint32_t)(((2 * k + kcb) ^ ks) << 4);       \
            uint32_t kf[4];                                                    \
            ldsm_x4(kf, kb + off);                                             \
            mma16816(sacc[0], qf + 4 * k, kf[0], kf[1]);                       \
            mma16816(sacc[1], qf + 4 * k, kf[2], kf[3]);                       \
        }                                                                      \
        _Pragma("unroll")                                                      \
        for (int k = 0; k < 4; k++) {                                          \
            uint32_t off = krow + (uint32_t)(((2 * k + kcb) ^ ks) << 4);       \
            uint32_t kf[4];                                                    \
            ldsm_x4(kf, kb + 2048u + off);                                     \
            mma16816(sacc[2], qf + 4 * k, kf[0], kf[1]);                       \
            mma16816(sacc[3], qf + 4 * k, kf[2], kf[3]);                       \
        }                                                                      \
        _Pragma("unroll")                                                      \
        for (int n = 0; n < 2; n++) {                                          \
            float2 m0 = *(const float2*)(mt + 32 * n);                         \
            float2 m1 = *(const float2*)(mt + 8 * M_ROW + 32 * n);             \
            float e0 = ex2(sacc[n][0] * m0.x);                                 \
            float e1 = ex2(sacc[n][1] * m0.y);                                 \
            float e2 = ex2(sacc[n][2] * m1.x);                                 \
            float e3 = ex2(sacc[n][3] * m1.y);                                 \
            p01[n] = packh2(e0, e1);                                           \
            p23[n] = packh2(e2, e3);                                           \
        }                                                                      \
        {                                                                      \
            uint32_t pa[4] = {p01[0], p23[0], p01[1], p23[1]};                 \
            mma16816(racc, pa, kOnesH2, kOnesH2);                              \
            _Pragma("unroll")                                                  \
            for (int p = 0; p < 4; p++) {                                      \
                uint32_t vf[4];                                                \
                uint32_t off = vrow + (uint32_t)(((2 * p + qcb) ^ qs) << 4);   \
                ldsm_x4t(vf, vb + off);                                        \
                mma16816(oacc[2 * p],     pa, vf[0], vf[1]);                   \
                mma16816(oacc[2 * p + 1], pa, vf[2], vf[3]);                   \
            }                                                                  \
        }                                                                      \
        _Pragma("unroll")                                                      \
        for (int n = 2; n < 4; n++) {                                          \
            float2 m0 = *(const float2*)(mt + 32 * n);                         \
            float2 m1 = *(const float2*)(mt + 8 * M_ROW + 32 * n);             \
            float e0 = ex2(sacc[n][0] * m0.x);                                 \
            float e1 = ex2(sacc[n][1] * m0.y);                                 \
            float e2 = ex2(sacc[n][2] * m1.x);                                 \
            float e3 = ex2(sacc[n][3] * m1.y);                                 \
            p01[n] = packh2(e0, e1);                                           \
            p23[n] = packh2(e2, e3);                                           \
        }                                                                      \
        {                                                                      \
            uint32_t pa[4] = {p01[2], p23[2], p01[3], p23[3]};                 \
            mma16816(racc, pa, kOnesH2, kOnesH2);                              \
            _Pragma("unroll")                                                  \
            for (int p = 0; p < 4; p++) {                                      \
                uint32_t vf[4];                                                \
                uint32_t off = vrow + (uint32_t)(((2 * p + qcb) ^ qs) << 4);   \
                ldsm_x4t(vf, vb + 2048u + off);                                \
                mma16816(oacc[2 * p],     pa, vf[0], vf[1]);                   \
                mma16816(oacc[2 * p + 1], pa, vf[2], vf[3]);                   \
            }                                                                  \
        }                                                                      \
        if ((T) + 2 < NT) {                                                    \
            kv_load(sb + OFF_KV + (uint32_t)(WSLOT) * KV_STRIDE,               \
                    gKh, gVh, ((T) + 2) * BK, tid);                            \
            mask_load(sb + OFF_M + (uint32_t)(WSLOT) * M_STRIDE,               \
                      Mrow, ((T) + 2) * BK, tid);                              \
        }                                                                      \
        CPCOMMIT();                                                            \
    } while (0)

    // 64 tiles = 21 x 3 + 1; slot(t) = t % 3, write slot = (t+2) % 3
    for (int tt = 0; tt < 21; tt++) {
        const int t0 = 3 * tt;
        TILE_BODY(t0 + 0, 0, 2);
        TILE_BODY(t0 + 1, 1, 0);
        TILE_BODY(t0 + 2, 2, 1);
    }
    TILE_BODY(63, 0, 2);
    #undef TILE_BODY

    // ---- epilogue: reduce key halves, normalize, store ----
    const float rs0 = racc[0];   // full row sum (this warp's 32-key half)
    const float rs1 = racc[2];

    __syncthreads();
    float* sO = (float*)(smem + OFF_RO) + wq * 1024;   // [16][64]
    float* sRS = (float*)(smem + OFF_RS);

    if (h == 1) {
        if ((lane & 3) == 0) {
            sRS[wq * 16 + r0] = rs0;
            sRS[wq * 16 + 8 + r0] = rs1;
        }
        #pragma unroll
        for (int n = 0; n < 8; n++) {
            *(float2*)(sO + r0 * 64 + 8 * n + c0) =
                make_float2(oacc[n][0], oacc[n][1]);
            *(float2*)(sO + (r0 + 8) * 64 + 8 * n + c0) =
                make_float2(oacc[n][2], oacc[n][3]);
        }
    }
    __syncthreads();

    if (h == 0) {
        float i0 = 1.f / (rs0 + sRS[wq * 16 + r0]);
        float i1 = 1.f / (rs1 + sRS[wq * 16 + 8 + r0]);
        float* o0 = gO + ((size_t)b * kL + q0 + 16 * wq + r0) * kD + c0;
        float* o1 = o0 + 8 * (size_t)kD;
        #pragma unroll
        for (int n = 0; n < 8; n++) {
            float2 a = *(const float2*)(sO + r0 * 64 + 8 * n + c0);
            float2 c = *(const float2*)(sO + (r0 + 8) * 64 + 8 * n + c0);
            *(float2*)(o0 + 8 * n) = make_float2((oacc[n][0] + a.x) * i0,
                                                 (oacc[n][1] + a.y) * i0);
            *(float2*)(o1 + 8 * n) = make_float2((oacc[n][2] + c.x) * i1,
                                                 (oacc[n][3] + c.y) * i1);
        }
    }
}

}  // namespace

extern "C" void kernel_launch(void* const* d_in, const int* in_sizes, int n_in,
                              void* d_out, int out_size) {
    const float* Q = (const float*)d_in[0];
    const float* K = (const float*)d_in[1];
    const float* V = (const float*)d_in[2];
    const float* M = (const float*)d_in[3];
    float* O = (float*)d_out;

    prep_kernel<<<1024, 256>>>(Q, K, V);

    cudaFuncSetAttribute(attn_kernel,
                         cudaFuncAttributeMaxDynamicSharedMemorySize, SMEM_TOTAL);
    dim3 grid(kL / BQ, kB);
    attn_kernel<<<grid, NTHREADS, SMEM_TOTAL>>>(M, O);
}